// round 15
// baseline (speedup 1.0000x reference)
#include <cuda_runtime.h>
#include <cuda_bf16.h>
#include <cstdint>

// Problem constants
#define Bq 32
#define Tt 784
#define Cc 384
#define NHh 6
#define HDd 64
#define Mm (Bq * Tt)          // 25088
#define TP 832                // T padded to 13*64
#define BH (Bq * NHh)         // 192
#define IMG_H 28
#define IMG_W 28
#define SCALE_F 0.05103103630798288f   // 384^-0.5
#define QSCALE (SCALE_F * 1.4426950408889634f)   // fold log2(e) for exp2 softmax

// Fragment layout (FL) for GEMM operands X[M][384]:
//   FL[mb*6144 + kb*128 + g*16 + t*4 + h + 2u] = X[16mb+8h+g][8kb+t+4u]

// ---------------------------------------------------------------------------
// Scratch
// ---------------------------------------------------------------------------
__device__ float g_qt[(size_t)Mm * Cc];        // frag layout
__device__ float g_kt[(size_t)Mm * Cc];
__device__ float g_vt[(size_t)Mm * Cc];
__device__ float g_wq[(size_t)Cc * Cc];        // frag layout
__device__ float g_wk[(size_t)Cc * Cc];
__device__ float g_wv[(size_t)Cc * Cc];
__device__ float g_wp[(size_t)Cc * Cc];
__device__ float g_qp[(size_t)BH * TP * HDd];  // [bh][t][d] plain fp32 * QSCALE
__device__ float g_kp[(size_t)BH * TP * HDd];  // [bh][t][d-perm] tf32 bits
__device__ float g_vT[(size_t)BH * HDd * TP];  // [bh][d][t-perm] tf32 bits
__device__ float g_o [(size_t)Mm * Cc];        // frag layout, tf32 bits

// ---------------------------------------------------------------------------
// helpers
// ---------------------------------------------------------------------------
__device__ __forceinline__ uint32_t f2tf32(float f) {
    uint32_t u;
    asm("cvt.rna.tf32.f32 %0, %1;" : "=r"(u) : "f"(f));
    return u;
}

__device__ __forceinline__ void mma_tf32(float c[4],
    uint32_t a0, uint32_t a1, uint32_t a2, uint32_t a3,
    uint32_t b0, uint32_t b1)
{
    asm volatile(
        "mma.sync.aligned.m16n8k8.row.col.f32.tf32.tf32.f32 "
        "{%0,%1,%2,%3}, {%4,%5,%6,%7}, {%8,%9}, {%0,%1,%2,%3};"
        : "+f"(c[0]), "+f"(c[1]), "+f"(c[2]), "+f"(c[3])
        : "r"(a0), "r"(a1), "r"(a2), "r"(a3), "r"(b0), "r"(b1));
}

__device__ __forceinline__ int pos16(int k) {
    return (k & 8) | ((k & 3) << 1) | ((k & 4) >> 2);
}
__device__ __forceinline__ int perm8(int n) {
    return (n >> 1) + ((n & 1) << 2);
}

__device__ __forceinline__ void cp_async16(uint32_t saddr, const void* gaddr) {
    asm volatile("cp.async.cg.shared.global [%0], [%1], 16;"
                 :: "r"(saddr), "l"(gaddr));
}

__device__ __forceinline__ uint32_t smem_u32(const void* p) {
    return (uint32_t)__cvta_generic_to_shared(p);
}

// frag address for element (m, k) of a [*,384] frag-layout matrix
__device__ __forceinline__ int frag_addr(int m, int k) {
    return (m >> 4) * 6144 + (k >> 3) * 128 + (m & 7) * 16 +
           (k & 3) * 4 + ((m >> 3) & 1) + 2 * ((k >> 2) & 1);
}

// ---------------------------------------------------------------------------
// conv + BN: scalar per (bt, c)
// ---------------------------------------------------------------------------
__global__ void __launch_bounds__(256) convbn_kernel(
    const float* __restrict__ x,
    const float* __restrict__ cwq, const float* __restrict__ gq,
    const float* __restrict__ beq, const float* __restrict__ meq,
    const float* __restrict__ vaq,
    const float* __restrict__ cwk, const float* __restrict__ gk,
    const float* __restrict__ bek, const float* __restrict__ mek,
    const float* __restrict__ vak,
    const float* __restrict__ cwv, const float* __restrict__ gv,
    const float* __restrict__ bev, const float* __restrict__ mev,
    const float* __restrict__ vav)
{
    int idx = blockIdx.x * 256 + threadIdx.x;
    if (idx >= Mm * Cc) return;
    int c  = idx % Cc;
    int bt = idx / Cc;
    int t  = bt % Tt;
    int b  = bt / Tt;
    int y  = t / IMG_W;
    int xp = t % IMG_W;

    int odx = frag_addr(bt, c);

    float vals[9];
#pragma unroll
    for (int dy = 0; dy < 3; dy++) {
#pragma unroll
        for (int dx = 0; dx < 3; dx++) {
            int yy = y + dy - 1, xx = xp + dx - 1;
            bool in = (yy >= 0) && (yy < IMG_H) && (xx >= 0) && (xx < IMG_W);
            vals[dy * 3 + dx] =
                in ? x[((size_t)b * Tt + yy * IMG_W + xx) * Cc + c] : 0.f;
        }
    }
    {
        float acc = 0.f;
#pragma unroll
        for (int i = 0; i < 9; i++) acc += vals[i] * cwq[c * 9 + i];
        float inv = gq[c] * rsqrtf(vaq[c] + 1e-5f);
        g_qt[odx] = __uint_as_float(f2tf32(acc * inv + (beq[c] - meq[c] * inv)));
    }
    {
        float acc = 0.f;
#pragma unroll
        for (int i = 0; i < 9; i++) acc += vals[i] * cwk[c * 9 + i];
        float inv = gk[c] * rsqrtf(vak[c] + 1e-5f);
        g_kt[odx] = __uint_as_float(f2tf32(acc * inv + (bek[c] - mek[c] * inv)));
    }
    {
        float acc = 0.f;
#pragma unroll
        for (int i = 0; i < 9; i++) acc += vals[i] * cwv[c * 9 + i];
        float inv = gv[c] * rsqrtf(vav[c] + 1e-5f);
        g_vt[odx] = __uint_as_float(f2tf32(acc * inv + (bev[c] - mev[c] * inv)));
    }
}

// ---------------------------------------------------------------------------
// Weight conversion: tf32 + frag layout
// ---------------------------------------------------------------------------
__global__ void __launch_bounds__(256) wconv_kernel(
    const float* __restrict__ wq, const float* __restrict__ wk,
    const float* __restrict__ wv, const float* __restrict__ wp)
{
    int i = blockIdx.x * 256 + threadIdx.x;
    if (i >= Cc * Cc) return;
    int k = i % Cc, n = i / Cc;
    int ip = frag_addr(n, k);
    g_wq[ip] = __uint_as_float(f2tf32(wq[i]));
    g_wk[ip] = __uint_as_float(f2tf32(wk[i]));
    g_wv[ip] = __uint_as_float(f2tf32(wv[i]));
    g_wp[ip] = __uint_as_float(f2tf32(wp[i]));
}

// ---------------------------------------------------------------------------
// GEMM core: 128x128 tile, frag-layout inputs, cp.async 4-stage ring,
// one barrier per BK=16 slab, LDS.128 fragment loads. 256 threads.
// ---------------------------------------------------------------------------
#define SLAB_U32 2048
#define GEMM_DSMEM (8 * SLAB_U32 * 4)   // 65536 B

__device__ __forceinline__ void gemm128_frag(
    const float* __restrict__ A, const float* __restrict__ B,
    int bm, int bn, uint32_t* As, uint32_t* Bs, float acc[4][4][4])
{
    const int tid  = threadIdx.x;
    const int lane = tid & 31;
    const int warp = tid >> 5;
    const int g    = lane >> 2;
    const int tq   = lane & 3;

    const int mbl  = tid >> 6;
    const int koff = ((tid >> 5) & 1) * 128 + (tid & 31) * 4;
    const float* Ag0 = A + (size_t)(bm / 16 + mbl) * 6144 + koff;
    const float* Ag1 = Ag0 + 4 * 6144;
    const float* Bg0 = B + (size_t)(bn / 16 + mbl) * 6144 + koff;
    const float* Bg1 = Bg0 + 4 * 6144;
    uint32_t sa0 = smem_u32(As) + tid * 16;
    uint32_t sa1 = sa0 + 256 * 16;
    uint32_t sb0 = smem_u32(Bs) + tid * 16;
    uint32_t sb1 = sb0 + 256 * 16;

    const int nslab = Cc >> 4;   // 24

#define GEMM_ISSUE(s) do {                                   \
        uint32_t _off = (uint32_t)(((s) & 3) * 8192);        \
        cp_async16(sa0 + _off, Ag0 + (s) * 256);             \
        cp_async16(sa1 + _off, Ag1 + (s) * 256);             \
        cp_async16(sb0 + _off, Bg0 + (s) * 256);             \
        cp_async16(sb1 + _off, Bg1 + (s) * 256);             \
        asm volatile("cp.async.commit_group;");              \
    } while (0)

    GEMM_ISSUE(0);
    GEMM_ISSUE(1);
    GEMM_ISSUE(2);

    const int awb = (warp & 1) * 4;
    const int bwb = (warp >> 1) * 2;
    const int fidx = (g * 4 + tq) * 4;

    for (int s = 0; s < nslab; s++) {
        asm volatile("cp.async.wait_group 2;");
        __syncthreads();
        const uint32_t* Ab = As + (s & 3) * SLAB_U32;
        const uint32_t* Bb = Bs + (s & 3) * SLAB_U32;
#pragma unroll
        for (int kbl = 0; kbl < 2; kbl++) {
            uint4 aq[4];
#pragma unroll
            for (int ms = 0; ms < 4; ms++)
                aq[ms] = *(const uint4*)&Ab[((awb + ms) * 2 + kbl) * 128 + fidx];
            uint4 bq[2];
#pragma unroll
            for (int jp = 0; jp < 2; jp++)
                bq[jp] = *(const uint4*)&Bb[((bwb + jp) * 2 + kbl) * 128 + fidx];
#pragma unroll
            for (int jp = 0; jp < 2; jp++) {
#pragma unroll
                for (int ms = 0; ms < 4; ms++) {
                    mma_tf32(acc[ms][2 * jp],
                             aq[ms].x, aq[ms].y, aq[ms].z, aq[ms].w,
                             bq[jp].x, bq[jp].z);
                    mma_tf32(acc[ms][2 * jp + 1],
                             aq[ms].x, aq[ms].y, aq[ms].z, aq[ms].w,
                             bq[jp].y, bq[jp].w);
                }
            }
        }
        if (s + 3 < nslab) GEMM_ISSUE(s + 3);
        else asm volatile("cp.async.commit_group;");
    }
#undef GEMM_ISSUE
}

// ---------------------------------------------------------------------------
// Q/K/V projection (blockIdx.z selects q/k/v)
// ---------------------------------------------------------------------------
__global__ void __launch_bounds__(256) qkv_mma_kernel()
{
    extern __shared__ uint32_t dsm[];
    uint32_t* As = dsm;
    uint32_t* Bs = dsm + 4 * SLAB_U32;

    int which = blockIdx.z;
    const float* A = (which == 0) ? g_qt : (which == 1) ? g_kt : g_vt;
    const float* W = (which == 0) ? g_wq : (which == 1) ? g_wk : g_wv;

    int bm = blockIdx.x * 128, bn = blockIdx.y * 128;
    float acc[4][4][4] = {};
    gemm128_frag(A, W, bm, bn, As, Bs, acc);

    int lane = threadIdx.x & 31, warp = threadIdx.x >> 5;
    int g = lane >> 2, tq = lane & 3;
    int wm = (warp & 1) * 64, wn = (warp >> 1) * 32;
    int h = (bn + wn) >> 6;

#pragma unroll
    for (int ms = 0; ms < 4; ms++) {
#pragma unroll
        for (int rr = 0; rr < 2; rr++) {
            int m = bm + wm + ms * 16 + g + rr * 8;
            int b = m / Tt, t = m - b * Tt;
            int bh = b * NHh + h;
            if (which == 0) {
                float* dst = g_qp + ((size_t)bh * TP + t) * HDd;
#pragma unroll
                for (int j = 0; j < 4; j++) {
                    int d = (bn + wn + j * 8 + 2 * tq) & 63;
                    *(float2*)(dst + d) = make_float2(
                        acc[ms][j][rr * 2 + 0] * QSCALE,
                        acc[ms][j][rr * 2 + 1] * QSCALE);
                }
            } else if (which == 1) {
                float* dst = g_kp + ((size_t)bh * TP + t) * HDd;
#pragma unroll
                for (int j = 0; j < 4; j++) {
                    int c0 = (bn + wn + j * 8 + 2 * tq) & 63;
                    int p0 = (c0 & 48) | pos16(c0 & 15);
                    int p1 = (c0 & 48) | pos16((c0 + 1) & 15);
                    dst[p0] = __uint_as_float(f2tf32(acc[ms][j][rr * 2 + 0]));
                    dst[p1] = __uint_as_float(f2tf32(acc[ms][j][rr * 2 + 1]));
                }
            } else {
                int tp = (t & ~15) | pos16(t & 15);
                float* dst = g_vT + (size_t)bh * HDd * TP + tp;
#pragma unroll
                for (int j = 0; j < 4; j++) {
                    int d = (bn + wn + j * 8 + 2 * tq) & 63;
                    dst[(size_t)d * TP] =
                        __uint_as_float(f2tf32(acc[ms][j][rr * 2 + 0]));
                    dst[(size_t)(d + 1) * TP] =
                        __uint_as_float(f2tf32(acc[ms][j][rr * 2 + 1]));
                }
            }
        }
    }
}

// ---------------------------------------------------------------------------
// Output projection
// ---------------------------------------------------------------------------
__global__ void __launch_bounds__(256) proj_mma_kernel(
    const float* __restrict__ bias, float* __restrict__ out)
{
    extern __shared__ uint32_t dsm[];
    uint32_t* As = dsm;
    uint32_t* Bs = dsm + 4 * SLAB_U32;

    int bm = blockIdx.x * 128, bn = blockIdx.y * 128;
    float acc[4][4][4] = {};
    gemm128_frag(g_o, g_wp, bm, bn, As, Bs, acc);

    int lane = threadIdx.x & 31, warp = threadIdx.x >> 5;
    int g = lane >> 2, tq = lane & 3;
    int wm = (warp & 1) * 64, wn = (warp >> 1) * 32;
#pragma unroll
    for (int ms = 0; ms < 4; ms++) {
#pragma unroll
        for (int rr = 0; rr < 2; rr++) {
            int m = bm + wm + ms * 16 + g + rr * 8;
#pragma unroll
            for (int j = 0; j < 4; j++) {
                int n = bn + wn + j * 8 + 2 * tq;
                float2 bb = *(const float2*)(bias + n);
                *(float2*)(out + (size_t)m * Cc + n) = make_float2(
                    acc[ms][j][rr * 2 + 0] + bb.x,
                    acc[ms][j][rr * 2 + 1] + bb.y);
            }
        }
    }
}

// ---------------------------------------------------------------------------
// Flash attention. Block = (bh, 112 q rows), 224 threads = 7 warps x 16 rows.
// DYNAMIC smem (73728 B) so 2 CTAs/SM fit. Loop-based cp.async staging.
// ---------------------------------------------------------------------------
#define STRF 72
#define FBUF (64 * STRF)
#define FTHREADS 224
#define FLASH_DSMEM (4 * FBUF * 4)   // Ks(2 bufs) + Vs(2 bufs) = 73728 B

__global__ void __launch_bounds__(FTHREADS) flash_kernel()
{
    extern __shared__ uint32_t fsm[];
    uint32_t* Ks = fsm;               // 2*FBUF; also output stage
    uint32_t* Vs = fsm + 2 * FBUF;

    int bh = blockIdx.y;
    int q0 = blockIdx.x * 112;
    int tid = threadIdx.x, lane = tid & 31, warp = tid >> 5;  // warp 0..6
    int g = lane >> 2, tq = lane & 3;

    const float* Qb = g_qp + (size_t)bh * TP * HDd;
    const float* Kb = g_kp + (size_t)bh * TP * HDd;
    const float* Vb = g_vT + (size_t)bh * HDd * TP;

    const uint32_t ks_base = smem_u32(Ks);
    const uint32_t vs_base = smem_u32(Vs);

    auto issue_chunk = [&](int ct) {
        uint32_t off = (ct & 1) * (FBUF * 4);
        const float* kc = Kb + (size_t)(ct * 64) * HDd;
        const float* vc = Vb + ct * 64;
        for (int i = tid; i < 1024; i += FTHREADS) {
            int row = i >> 4;
            int seg = (i & 15) * 4;
            int kr = (row & ~7) | perm8(row & 7);
            uint32_t soff = off + (uint32_t)(row * STRF + seg) * 4;
            cp_async16(ks_base + soff, kc + (size_t)kr * HDd + seg);
            cp_async16(vs_base + soff, vc + (size_t)row * TP + seg);
        }
        asm volatile("cp.async.commit_group;");
    };

    uint32_t qf[8][4];
    {
        const float* r0 = Qb + (size_t)(q0 + warp * 16 + g) * HDd;
        const float* r1 = r0 + 8 * HDd;
#pragma unroll
        for (int k8 = 0; k8 < 8; k8++) {
            qf[k8][0] = f2tf32(r0[k8 * 8 + tq]);
            qf[k8][2] = f2tf32(r0[k8 * 8 + tq + 4]);
            qf[k8][1] = f2tf32(r1[k8 * 8 + tq]);
            qf[k8][3] = f2tf32(r1[k8 * 8 + tq + 4]);
        }
    }

    issue_chunk(0);
    issue_chunk(1);

    float oacc[8][4];
#pragma unroll
    for (int j = 0; j < 8; j++)
#pragma unroll
        for (int i = 0; i < 4; i++) oacc[j][i] = 0.f;
    float m0 = -1e30f, m1 = -1e30f, l0 = 0.f, l1 = 0.f;

    for (int ct = 0; ct < 13; ct++) {
        if (ct < 12) asm volatile("cp.async.wait_group 1;");
        else         asm volatile("cp.async.wait_group 0;");
        __syncthreads();

        const uint32_t* Kbuf = Ks + (ct & 1) * FBUF;
        const uint32_t* Vbuf = Vs + (ct & 1) * FBUF;

        float sacc[8][4];
#pragma unroll
        for (int j = 0; j < 8; j++)
#pragma unroll
            for (int i = 0; i < 4; i++) sacc[j][i] = 0.f;

        if (ct != 12) {
#pragma unroll
            for (int kk = 0; kk < 64; kk += 8) {
#pragma unroll
                for (int j = 0; j < 8; j++) {
                    uint2 bv = *(const uint2*)&Kbuf[(j * 8 + g) * STRF + kk + 2 * tq];
                    mma_tf32(sacc[j], qf[kk >> 3][0], qf[kk >> 3][1],
                             qf[kk >> 3][2], qf[kk >> 3][3], bv.x, bv.y);
                }
            }
        } else {
#pragma unroll
            for (int kk = 0; kk < 64; kk += 8) {
#pragma unroll
                for (int j = 0; j < 2; j++) {
                    uint2 bv = *(const uint2*)&Kbuf[(j * 8 + g) * STRF + kk + 2 * tq];
                    mma_tf32(sacc[j], qf[kk >> 3][0], qf[kk >> 3][1],
                             qf[kk >> 3][2], qf[kk >> 3][3], bv.x, bv.y);
                }
            }
#pragma unroll
            for (int j = 2; j < 8; j++)
#pragma unroll
                for (int i = 0; i < 4; i++) sacc[j][i] = -1e30f;
        }

        float t0m = -1e30f, t1m = -1e30f;
#pragma unroll
        for (int j = 0; j < 8; j++) {
            t0m = fmaxf(t0m, fmaxf(sacc[j][0], sacc[j][1]));
            t1m = fmaxf(t1m, fmaxf(sacc[j][2], sacc[j][3]));
        }
        t0m = fmaxf(t0m, __shfl_xor_sync(0xffffffffu, t0m, 1));
        t0m = fmaxf(t0m, __shfl_xor_sync(0xffffffffu, t0m, 2));
        t1m = fmaxf(t1m, __shfl_xor_sync(0xffffffffu, t1m, 1));
        t1m = fmaxf(t1m, __shfl_xor_sync(0xffffffffu, t1m, 2));
        float mn0 = fmaxf(m0, t0m), mn1 = fmaxf(m1, t1m);
        float sc0 = exp2f(m0 - mn0), sc1 = exp2f(m1 - mn1);
        m0 = mn0; m1 = mn1;
        l0 *= sc0; l1 *= sc1;
        float ps0 = 0.f, ps1 = 0.f;
#pragma unroll
        for (int j = 0; j < 8; j++) {
            oacc[j][0] *= sc0; oacc[j][1] *= sc0;
            oacc[j][2] *= sc1; oacc[j][3] *= sc1;
            sacc[j][0] = exp2f(sacc[j][0] - mn0);
            sacc[j][1] = exp2f(sacc[j][1] - mn0);
            sacc[j][2] = exp2f(sacc[j][2] - mn1);
            sacc[j][3] = exp2f(sacc[j][3] - mn1);
            ps0 += sacc[j][0] + sacc[j][1];
            ps1 += sacc[j][2] + sacc[j][3];
        }
        l0 += ps0; l1 += ps1;

        if (ct != 12) {
#pragma unroll
            for (int kk = 0; kk < 64; kk += 8) {
                const int jj = kk >> 3;
                uint32_t pa0 = f2tf32(sacc[jj][0]);
                uint32_t pa1 = f2tf32(sacc[jj][2]);
                uint32_t pa2 = f2tf32(sacc[jj][1]);
                uint32_t pa3 = f2tf32(sacc[jj][3]);
#pragma unroll
                for (int j = 0; j < 8; j++) {
                    uint2 bv = *(const uint2*)&Vbuf[(j * 8 + g) * STRF + kk + 2 * tq];
                    mma_tf32(oacc[j], pa0, pa1, pa2, pa3, bv.x, bv.y);
                }
            }
        } else {
#pragma unroll
            for (int kk = 0; kk < 16; kk += 8) {
                const int jj = kk >> 3;
                uint32_t pa0 = f2tf32(sacc[jj][0]);
                uint32_t pa1 = f2tf32(sacc[jj][2]);
                uint32_t pa2 = f2tf32(sacc[jj][1]);
                uint32_t pa3 = f2tf32(sacc[jj][3]);
#pragma unroll
                for (int j = 0; j < 8; j++) {
                    uint2 bv = *(const uint2*)&Vbuf[(j * 8 + g) * STRF + kk + 2 * tq];
                    mma_tf32(oacc[j], pa0, pa1, pa2, pa3, bv.x, bv.y);
                }
            }
        }

        __syncthreads();
        if (ct + 2 < 13) issue_chunk(ct + 2);
    }

    l0 += __shfl_xor_sync(0xffffffffu, l0, 1);
    l0 += __shfl_xor_sync(0xffffffffu, l0, 2);
    l1 += __shfl_xor_sync(0xffffffffu, l1, 1);
    l1 += __shfl_xor_sync(0xffffffffu, l1, 2);
    float inv0 = 1.f / l0, inv1 = 1.f / l1;

    int b = bh / NHh, h = bh - (bh / NHh) * NHh;

    // ---- Epilogue: stage frag-layout tile in Ks, then coalesced write ----
    __syncthreads();
    {
        int t0v = (2 * tq) & 3, u0v = tq >> 1;
        int ibase = g * 16 + t0v * 4 + 2 * u0v;
        uint32_t* stg = Ks;
#pragma unroll
        for (int j = 0; j < 8; j++) {
            uint32_t* row = stg + (warp * 8 + j) * 128 + ibase;
            row[0] = f2tf32(oacc[j][0] * inv0);
            row[4] = f2tf32(oacc[j][1] * inv0);
            row[1] = f2tf32(oacc[j][2] * inv1);
            row[5] = f2tf32(oacc[j][3] * inv1);
        }
    }
    __syncthreads();
    {
        int m0b = (b * Tt + q0) >> 4;
        const int total = 7 * 8 * 32;      // float4 units (7 m-blocks)
        for (int i = tid; i < total; i += FTHREADS) {
            int rowc = i >> 5;
            int in4  = i & 31;
            int mbl = rowc >> 3, kbl = rowc & 7;
            uint4 v = *(const uint4*)&Ks[rowc * 128 + in4 * 4];
            *(uint4*)&g_o[(size_t)(m0b + mbl) * 6144 +
                          (h * 8 + kbl) * 128 + in4 * 4] = v;
        }
    }
}

// ---------------------------------------------------------------------------
// kernel_launch
// ---------------------------------------------------------------------------
extern "C" void kernel_launch(void* const* d_in, const int* in_sizes, int n_in,
                              void* d_out, int out_size)
{
    int base = 1;
    if (n_in >= 3 && in_sizes[1] == 1 && in_sizes[2] == 1) base = 3;

    const float* x = (const float*)d_in[0];
    const float* cw[3];
    const float* ga[3];
    const float* be[3];
    const float* me[3];
    const float* va[3];
    for (int i = 0; i < 3; i++) {
        cw[i] = (const float*)d_in[base + 5 * i + 0];
        ga[i] = (const float*)d_in[base + 5 * i + 1];
        be[i] = (const float*)d_in[base + 5 * i + 2];
        me[i] = (const float*)d_in[base + 5 * i + 3];
        va[i] = (const float*)d_in[base + 5 * i + 4];
    }
    const float* w_q    = (const float*)d_in[base + 15];
    const float* w_k    = (const float*)d_in[base + 16];
    const float* w_v    = (const float*)d_in[base + 17];
    const float* w_proj = (const float*)d_in[base + 18];
    const float* b_proj = (const float*)d_in[base + 19];
    float* out = (float*)d_out;

    static int attr_done = 0;
    if (!attr_done) {
        cudaFuncSetAttribute(qkv_mma_kernel,
                             cudaFuncAttributeMaxDynamicSharedMemorySize,
                             GEMM_DSMEM);
        cudaFuncSetAttribute(proj_mma_kernel,
                             cudaFuncAttributeMaxDynamicSharedMemorySize,
                             GEMM_DSMEM);
        cudaFuncSetAttribute(flash_kernel,
                             cudaFuncAttributeMaxDynamicSharedMemorySize,
                             FLASH_DSMEM);
        attr_done = 1;
    }

    wconv_kernel<<<(Cc * Cc + 255) / 256, 256>>>(w_q, w_k, w_v, w_proj);

    convbn_kernel<<<(Mm * Cc + 255) / 256, 256>>>(
        x,
        cw[0], ga[0], be[0], me[0], va[0],
        cw[1], ga[1], be[1], me[1], va[1],
        cw[2], ga[2], be[2], me[2], va[2]);

    qkv_mma_kernel<<<dim3(Mm / 128, Cc / 128, 3), 256, GEMM_DSMEM>>>();

    flash_kernel<<<dim3(7, BH), FTHREADS, FLASH_DSMEM>>>();

    proj_mma_kernel<<<dim3(Mm / 128, Cc / 128), 256, GEMM_DSMEM>>>(b_proj, out);
}

// round 16
// speedup vs baseline: 1.1134x; 1.1134x over previous
#include <cuda_runtime.h>
#include <cuda_bf16.h>
#include <cstdint>

// Problem constants
#define Bq 32
#define Tt 784
#define Cc 384
#define NHh 6
#define HDd 64
#define Mm (Bq * Tt)          // 25088
#define TP 832                // T padded to 13*64
#define BH (Bq * NHh)         // 192
#define IMG_H 28
#define IMG_W 28
#define SCALE_F 0.05103103630798288f   // 384^-0.5
#define QSCALE (SCALE_F * 1.4426950408889634f)   // fold log2(e) for exp2 softmax

// Fragment layout (FL) for GEMM operands X[M][384]:
//   FL[mb*6144 + kb*128 + g*16 + t*4 + h + 2u] = X[16mb+8h+g][8kb+t+4u]

// ---------------------------------------------------------------------------
// Scratch
// ---------------------------------------------------------------------------
__device__ float g_qt[(size_t)Mm * Cc];        // frag layout
__device__ float g_kt[(size_t)Mm * Cc];
__device__ float g_vt[(size_t)Mm * Cc];
__device__ float g_wq[(size_t)Cc * Cc];        // frag layout
__device__ float g_wk[(size_t)Cc * Cc];
__device__ float g_wv[(size_t)Cc * Cc];
__device__ float g_wp[(size_t)Cc * Cc];
__device__ float g_qp[(size_t)BH * TP * HDd];  // [bh][t][d] plain fp32 * QSCALE
__device__ float g_kp[(size_t)BH * TP * HDd];  // [bh][t][d-perm] tf32 bits
__device__ float g_vT[(size_t)BH * HDd * TP];  // [bh][d][t-perm] tf32 bits
__device__ float g_o [(size_t)Mm * Cc];        // frag layout, tf32 bits

// ---------------------------------------------------------------------------
// helpers
// ---------------------------------------------------------------------------
__device__ __forceinline__ uint32_t f2tf32(float f) {
    uint32_t u;
    asm("cvt.rna.tf32.f32 %0, %1;" : "=r"(u) : "f"(f));
    return u;
}

__device__ __forceinline__ void mma_tf32(float c[4],
    uint32_t a0, uint32_t a1, uint32_t a2, uint32_t a3,
    uint32_t b0, uint32_t b1)
{
    asm volatile(
        "mma.sync.aligned.m16n8k8.row.col.f32.tf32.tf32.f32 "
        "{%0,%1,%2,%3}, {%4,%5,%6,%7}, {%8,%9}, {%0,%1,%2,%3};"
        : "+f"(c[0]), "+f"(c[1]), "+f"(c[2]), "+f"(c[3])
        : "r"(a0), "r"(a1), "r"(a2), "r"(a3), "r"(b0), "r"(b1));
}

__device__ __forceinline__ int pos16(int k) {
    return (k & 8) | ((k & 3) << 1) | ((k & 4) >> 2);
}
__device__ __forceinline__ int perm8(int n) {
    return (n >> 1) + ((n & 1) << 2);
}

__device__ __forceinline__ void cp_async16(uint32_t saddr, const void* gaddr) {
    asm volatile("cp.async.cg.shared.global [%0], [%1], 16;"
                 :: "r"(saddr), "l"(gaddr));
}

__device__ __forceinline__ uint32_t smem_u32(const void* p) {
    return (uint32_t)__cvta_generic_to_shared(p);
}

// frag address for element (m, k) of a [*,384] frag-layout matrix
__device__ __forceinline__ int frag_addr(int m, int k) {
    return (m >> 4) * 6144 + (k >> 3) * 128 + (m & 7) * 16 +
           (k & 3) * 4 + ((m >> 3) & 1) + 2 * ((k >> 2) & 1);
}

// ---------------------------------------------------------------------------
// conv + BN: scalar per (bt, c)
// ---------------------------------------------------------------------------
__global__ void __launch_bounds__(256) convbn_kernel(
    const float* __restrict__ x,
    const float* __restrict__ cwq, const float* __restrict__ gq,
    const float* __restrict__ beq, const float* __restrict__ meq,
    const float* __restrict__ vaq,
    const float* __restrict__ cwk, const float* __restrict__ gk,
    const float* __restrict__ bek, const float* __restrict__ mek,
    const float* __restrict__ vak,
    const float* __restrict__ cwv, const float* __restrict__ gv,
    const float* __restrict__ bev, const float* __restrict__ mev,
    const float* __restrict__ vav)
{
    int idx = blockIdx.x * 256 + threadIdx.x;
    if (idx >= Mm * Cc) return;
    int c  = idx % Cc;
    int bt = idx / Cc;
    int t  = bt % Tt;
    int b  = bt / Tt;
    int y  = t / IMG_W;
    int xp = t % IMG_W;

    int odx = frag_addr(bt, c);

    float vals[9];
#pragma unroll
    for (int dy = 0; dy < 3; dy++) {
#pragma unroll
        for (int dx = 0; dx < 3; dx++) {
            int yy = y + dy - 1, xx = xp + dx - 1;
            bool in = (yy >= 0) && (yy < IMG_H) && (xx >= 0) && (xx < IMG_W);
            vals[dy * 3 + dx] =
                in ? x[((size_t)b * Tt + yy * IMG_W + xx) * Cc + c] : 0.f;
        }
    }
    {
        float acc = 0.f;
#pragma unroll
        for (int i = 0; i < 9; i++) acc += vals[i] * cwq[c * 9 + i];
        float inv = gq[c] * rsqrtf(vaq[c] + 1e-5f);
        g_qt[odx] = __uint_as_float(f2tf32(acc * inv + (beq[c] - meq[c] * inv)));
    }
    {
        float acc = 0.f;
#pragma unroll
        for (int i = 0; i < 9; i++) acc += vals[i] * cwk[c * 9 + i];
        float inv = gk[c] * rsqrtf(vak[c] + 1e-5f);
        g_kt[odx] = __uint_as_float(f2tf32(acc * inv + (bek[c] - mek[c] * inv)));
    }
    {
        float acc = 0.f;
#pragma unroll
        for (int i = 0; i < 9; i++) acc += vals[i] * cwv[c * 9 + i];
        float inv = gv[c] * rsqrtf(vav[c] + 1e-5f);
        g_vt[odx] = __uint_as_float(f2tf32(acc * inv + (bev[c] - mev[c] * inv)));
    }
}

// ---------------------------------------------------------------------------
// Weight conversion: tf32 + frag layout
// ---------------------------------------------------------------------------
__global__ void __launch_bounds__(256) wconv_kernel(
    const float* __restrict__ wq, const float* __restrict__ wk,
    const float* __restrict__ wv, const float* __restrict__ wp)
{
    int i = blockIdx.x * 256 + threadIdx.x;
    if (i >= Cc * Cc) return;
    int k = i % Cc, n = i / Cc;
    int ip = frag_addr(n, k);
    g_wq[ip] = __uint_as_float(f2tf32(wq[i]));
    g_wk[ip] = __uint_as_float(f2tf32(wk[i]));
    g_wv[ip] = __uint_as_float(f2tf32(wv[i]));
    g_wp[ip] = __uint_as_float(f2tf32(wp[i]));
}

// ---------------------------------------------------------------------------
// GEMM core: 128x128 tile, frag-layout inputs, cp.async 4-stage ring,
// one barrier per BK=16 slab, LDS.128 fragment loads. 256 threads.
// ---------------------------------------------------------------------------
#define SLAB_U32 2048
#define GEMM_DSMEM (8 * SLAB_U32 * 4)   // 65536 B

__device__ __forceinline__ void gemm128_frag(
    const float* __restrict__ A, const float* __restrict__ B,
    int bm, int bn, uint32_t* As, uint32_t* Bs, float acc[4][4][4])
{
    const int tid  = threadIdx.x;
    const int lane = tid & 31;
    const int warp = tid >> 5;
    const int g    = lane >> 2;
    const int tq   = lane & 3;

    const int mbl  = tid >> 6;
    const int koff = ((tid >> 5) & 1) * 128 + (tid & 31) * 4;
    const float* Ag0 = A + (size_t)(bm / 16 + mbl) * 6144 + koff;
    const float* Ag1 = Ag0 + 4 * 6144;
    const float* Bg0 = B + (size_t)(bn / 16 + mbl) * 6144 + koff;
    const float* Bg1 = Bg0 + 4 * 6144;
    uint32_t sa0 = smem_u32(As) + tid * 16;
    uint32_t sa1 = sa0 + 256 * 16;
    uint32_t sb0 = smem_u32(Bs) + tid * 16;
    uint32_t sb1 = sb0 + 256 * 16;

    const int nslab = Cc >> 4;   // 24

#define GEMM_ISSUE(s) do {                                   \
        uint32_t _off = (uint32_t)(((s) & 3) * 8192);        \
        cp_async16(sa0 + _off, Ag0 + (s) * 256);             \
        cp_async16(sa1 + _off, Ag1 + (s) * 256);             \
        cp_async16(sb0 + _off, Bg0 + (s) * 256);             \
        cp_async16(sb1 + _off, Bg1 + (s) * 256);             \
        asm volatile("cp.async.commit_group;");              \
    } while (0)

    GEMM_ISSUE(0);
    GEMM_ISSUE(1);
    GEMM_ISSUE(2);

    const int awb = (warp & 1) * 4;
    const int bwb = (warp >> 1) * 2;
    const int fidx = (g * 4 + tq) * 4;

    for (int s = 0; s < nslab; s++) {
        asm volatile("cp.async.wait_group 2;");
        __syncthreads();
        const uint32_t* Ab = As + (s & 3) * SLAB_U32;
        const uint32_t* Bb = Bs + (s & 3) * SLAB_U32;
#pragma unroll
        for (int kbl = 0; kbl < 2; kbl++) {
            uint4 aq[4];
#pragma unroll
            for (int ms = 0; ms < 4; ms++)
                aq[ms] = *(const uint4*)&Ab[((awb + ms) * 2 + kbl) * 128 + fidx];
            uint4 bq[2];
#pragma unroll
            for (int jp = 0; jp < 2; jp++)
                bq[jp] = *(const uint4*)&Bb[((bwb + jp) * 2 + kbl) * 128 + fidx];
#pragma unroll
            for (int jp = 0; jp < 2; jp++) {
#pragma unroll
                for (int ms = 0; ms < 4; ms++) {
                    mma_tf32(acc[ms][2 * jp],
                             aq[ms].x, aq[ms].y, aq[ms].z, aq[ms].w,
                             bq[jp].x, bq[jp].z);
                    mma_tf32(acc[ms][2 * jp + 1],
                             aq[ms].x, aq[ms].y, aq[ms].z, aq[ms].w,
                             bq[jp].y, bq[jp].w);
                }
            }
        }
        if (s + 3 < nslab) GEMM_ISSUE(s + 3);
        else asm volatile("cp.async.commit_group;");
    }
#undef GEMM_ISSUE
}

// ---------------------------------------------------------------------------
// Q/K/V projection (blockIdx.z selects q/k/v)
// ---------------------------------------------------------------------------
__global__ void __launch_bounds__(256) qkv_mma_kernel()
{
    extern __shared__ uint32_t dsm[];
    uint32_t* As = dsm;
    uint32_t* Bs = dsm + 4 * SLAB_U32;

    int which = blockIdx.z;
    const float* A = (which == 0) ? g_qt : (which == 1) ? g_kt : g_vt;
    const float* W = (which == 0) ? g_wq : (which == 1) ? g_wk : g_wv;

    int bm = blockIdx.x * 128, bn = blockIdx.y * 128;
    float acc[4][4][4] = {};
    gemm128_frag(A, W, bm, bn, As, Bs, acc);

    int lane = threadIdx.x & 31, warp = threadIdx.x >> 5;
    int g = lane >> 2, tq = lane & 3;
    int wm = (warp & 1) * 64, wn = (warp >> 1) * 32;
    int h = (bn + wn) >> 6;

#pragma unroll
    for (int ms = 0; ms < 4; ms++) {
#pragma unroll
        for (int rr = 0; rr < 2; rr++) {
            int m = bm + wm + ms * 16 + g + rr * 8;
            int b = m / Tt, t = m - b * Tt;
            int bh = b * NHh + h;
            if (which == 0) {
                float* dst = g_qp + ((size_t)bh * TP + t) * HDd;
#pragma unroll
                for (int j = 0; j < 4; j++) {
                    int d = (bn + wn + j * 8 + 2 * tq) & 63;
                    *(float2*)(dst + d) = make_float2(
                        acc[ms][j][rr * 2 + 0] * QSCALE,
                        acc[ms][j][rr * 2 + 1] * QSCALE);
                }
            } else if (which == 1) {
                float* dst = g_kp + ((size_t)bh * TP + t) * HDd;
#pragma unroll
                for (int j = 0; j < 4; j++) {
                    int c0 = (bn + wn + j * 8 + 2 * tq) & 63;
                    int p0 = (c0 & 48) | pos16(c0 & 15);
                    int p1 = (c0 & 48) | pos16((c0 + 1) & 15);
                    dst[p0] = __uint_as_float(f2tf32(acc[ms][j][rr * 2 + 0]));
                    dst[p1] = __uint_as_float(f2tf32(acc[ms][j][rr * 2 + 1]));
                }
            } else {
                int tp = (t & ~15) | pos16(t & 15);
                float* dst = g_vT + (size_t)bh * HDd * TP + tp;
#pragma unroll
                for (int j = 0; j < 4; j++) {
                    int d = (bn + wn + j * 8 + 2 * tq) & 63;
                    dst[(size_t)d * TP] =
                        __uint_as_float(f2tf32(acc[ms][j][rr * 2 + 0]));
                    dst[(size_t)(d + 1) * TP] =
                        __uint_as_float(f2tf32(acc[ms][j][rr * 2 + 1]));
                }
            }
        }
    }
}

// ---------------------------------------------------------------------------
// Output projection
// ---------------------------------------------------------------------------
__global__ void __launch_bounds__(256) proj_mma_kernel(
    const float* __restrict__ bias, float* __restrict__ out)
{
    extern __shared__ uint32_t dsm[];
    uint32_t* As = dsm;
    uint32_t* Bs = dsm + 4 * SLAB_U32;

    int bm = blockIdx.x * 128, bn = blockIdx.y * 128;
    float acc[4][4][4] = {};
    gemm128_frag(g_o, g_wp, bm, bn, As, Bs, acc);

    int lane = threadIdx.x & 31, warp = threadIdx.x >> 5;
    int g = lane >> 2, tq = lane & 3;
    int wm = (warp & 1) * 64, wn = (warp >> 1) * 32;
#pragma unroll
    for (int ms = 0; ms < 4; ms++) {
#pragma unroll
        for (int rr = 0; rr < 2; rr++) {
            int m = bm + wm + ms * 16 + g + rr * 8;
#pragma unroll
            for (int j = 0; j < 4; j++) {
                int n = bn + wn + j * 8 + 2 * tq;
                float2 bb = *(const float2*)(bias + n);
                *(float2*)(out + (size_t)m * Cc + n) = make_float2(
                    acc[ms][j][rr * 2 + 0] + bb.x,
                    acc[ms][j][rr * 2 + 1] + bb.y);
            }
        }
    }
}

// ---------------------------------------------------------------------------
// Flash attention. Block = (bh, 112 q rows), 224 threads = 7 warps x 16 rows.
// __launch_bounds__(224, 2): cap regs at 128 so 2 CTAs/SM fit the per-SMSP
// register file (4 warps x 128 x 32 = 16384). Dynamic smem 72KB x 2 = 144KB.
// ---------------------------------------------------------------------------
#define STRF 72
#define FBUF (64 * STRF)
#define FTHREADS 224
#define FLASH_DSMEM (4 * FBUF * 4)   // 73728 B

__global__ void __launch_bounds__(FTHREADS, 2) flash_kernel()
{
    extern __shared__ uint32_t fsm[];
    uint32_t* Ks = fsm;               // 2*FBUF; also output stage
    uint32_t* Vs = fsm + 2 * FBUF;

    int bh = blockIdx.y;
    int q0 = blockIdx.x * 112;
    int tid = threadIdx.x, lane = tid & 31, warp = tid >> 5;  // warp 0..6
    int g = lane >> 2, tq = lane & 3;

    const float* Qb = g_qp + (size_t)bh * TP * HDd;
    const float* Kb = g_kp + (size_t)bh * TP * HDd;
    const float* Vb = g_vT + (size_t)bh * HDd * TP;

    const uint32_t ks_base = smem_u32(Ks);
    const uint32_t vs_base = smem_u32(Vs);

    auto issue_chunk = [&](int ct) {
        uint32_t off = (ct & 1) * (FBUF * 4);
        const float* kc = Kb + (size_t)(ct * 64) * HDd;
        const float* vc = Vb + ct * 64;
        for (int i = tid; i < 1024; i += FTHREADS) {
            int row = i >> 4;
            int seg = (i & 15) * 4;
            int kr = (row & ~7) | perm8(row & 7);
            uint32_t soff = off + (uint32_t)(row * STRF + seg) * 4;
            cp_async16(ks_base + soff, kc + (size_t)kr * HDd + seg);
            cp_async16(vs_base + soff, vc + (size_t)row * TP + seg);
        }
        asm volatile("cp.async.commit_group;");
    };

    uint32_t qf[8][4];
    {
        const float* r0 = Qb + (size_t)(q0 + warp * 16 + g) * HDd;
        const float* r1 = r0 + 8 * HDd;
#pragma unroll
        for (int k8 = 0; k8 < 8; k8++) {
            qf[k8][0] = f2tf32(r0[k8 * 8 + tq]);
            qf[k8][2] = f2tf32(r0[k8 * 8 + tq + 4]);
            qf[k8][1] = f2tf32(r1[k8 * 8 + tq]);
            qf[k8][3] = f2tf32(r1[k8 * 8 + tq + 4]);
        }
    }

    issue_chunk(0);
    issue_chunk(1);

    float oacc[8][4];
#pragma unroll
    for (int j = 0; j < 8; j++)
#pragma unroll
        for (int i = 0; i < 4; i++) oacc[j][i] = 0.f;
    float m0 = -1e30f, m1 = -1e30f, l0 = 0.f, l1 = 0.f;

    for (int ct = 0; ct < 13; ct++) {
        if (ct < 12) asm volatile("cp.async.wait_group 1;");
        else         asm volatile("cp.async.wait_group 0;");
        __syncthreads();

        const uint32_t* Kbuf = Ks + (ct & 1) * FBUF;
        const uint32_t* Vbuf = Vs + (ct & 1) * FBUF;

        float sacc[8][4];
#pragma unroll
        for (int j = 0; j < 8; j++)
#pragma unroll
            for (int i = 0; i < 4; i++) sacc[j][i] = 0.f;

        if (ct != 12) {
#pragma unroll
            for (int kk = 0; kk < 64; kk += 8) {
#pragma unroll
                for (int j = 0; j < 8; j++) {
                    uint2 bv = *(const uint2*)&Kbuf[(j * 8 + g) * STRF + kk + 2 * tq];
                    mma_tf32(sacc[j], qf[kk >> 3][0], qf[kk >> 3][1],
                             qf[kk >> 3][2], qf[kk >> 3][3], bv.x, bv.y);
                }
            }
        } else {
#pragma unroll
            for (int kk = 0; kk < 64; kk += 8) {
#pragma unroll
                for (int j = 0; j < 2; j++) {
                    uint2 bv = *(const uint2*)&Kbuf[(j * 8 + g) * STRF + kk + 2 * tq];
                    mma_tf32(sacc[j], qf[kk >> 3][0], qf[kk >> 3][1],
                             qf[kk >> 3][2], qf[kk >> 3][3], bv.x, bv.y);
                }
            }
#pragma unroll
            for (int j = 2; j < 8; j++)
#pragma unroll
                for (int i = 0; i < 4; i++) sacc[j][i] = -1e30f;
        }

        float t0m = -1e30f, t1m = -1e30f;
#pragma unroll
        for (int j = 0; j < 8; j++) {
            t0m = fmaxf(t0m, fmaxf(sacc[j][0], sacc[j][1]));
            t1m = fmaxf(t1m, fmaxf(sacc[j][2], sacc[j][3]));
        }
        t0m = fmaxf(t0m, __shfl_xor_sync(0xffffffffu, t0m, 1));
        t0m = fmaxf(t0m, __shfl_xor_sync(0xffffffffu, t0m, 2));
        t1m = fmaxf(t1m, __shfl_xor_sync(0xffffffffu, t1m, 1));
        t1m = fmaxf(t1m, __shfl_xor_sync(0xffffffffu, t1m, 2));
        float mn0 = fmaxf(m0, t0m), mn1 = fmaxf(m1, t1m);
        float sc0 = exp2f(m0 - mn0), sc1 = exp2f(m1 - mn1);
        m0 = mn0; m1 = mn1;
        l0 *= sc0; l1 *= sc1;
        float ps0 = 0.f, ps1 = 0.f;
#pragma unroll
        for (int j = 0; j < 8; j++) {
            oacc[j][0] *= sc0; oacc[j][1] *= sc0;
            oacc[j][2] *= sc1; oacc[j][3] *= sc1;
            sacc[j][0] = exp2f(sacc[j][0] - mn0);
            sacc[j][1] = exp2f(sacc[j][1] - mn0);
            sacc[j][2] = exp2f(sacc[j][2] - mn1);
            sacc[j][3] = exp2f(sacc[j][3] - mn1);
            ps0 += sacc[j][0] + sacc[j][1];
            ps1 += sacc[j][2] + sacc[j][3];
        }
        l0 += ps0; l1 += ps1;

        if (ct != 12) {
#pragma unroll
            for (int kk = 0; kk < 64; kk += 8) {
                const int jj = kk >> 3;
                uint32_t pa0 = f2tf32(sacc[jj][0]);
                uint32_t pa1 = f2tf32(sacc[jj][2]);
                uint32_t pa2 = f2tf32(sacc[jj][1]);
                uint32_t pa3 = f2tf32(sacc[jj][3]);
#pragma unroll
                for (int j = 0; j < 8; j++) {
                    uint2 bv = *(const uint2*)&Vbuf[(j * 8 + g) * STRF + kk + 2 * tq];
                    mma_tf32(oacc[j], pa0, pa1, pa2, pa3, bv.x, bv.y);
                }
            }
        } else {
#pragma unroll
            for (int kk = 0; kk < 16; kk += 8) {
                const int jj = kk >> 3;
                uint32_t pa0 = f2tf32(sacc[jj][0]);
                uint32_t pa1 = f2tf32(sacc[jj][2]);
                uint32_t pa2 = f2tf32(sacc[jj][1]);
                uint32_t pa3 = f2tf32(sacc[jj][3]);
#pragma unroll
                for (int j = 0; j < 8; j++) {
                    uint2 bv = *(const uint2*)&Vbuf[(j * 8 + g) * STRF + kk + 2 * tq];
                    mma_tf32(oacc[j], pa0, pa1, pa2, pa3, bv.x, bv.y);
                }
            }
        }

        __syncthreads();
        if (ct + 2 < 13) issue_chunk(ct + 2);
    }

    l0 += __shfl_xor_sync(0xffffffffu, l0, 1);
    l0 += __shfl_xor_sync(0xffffffffu, l0, 2);
    l1 += __shfl_xor_sync(0xffffffffu, l1, 1);
    l1 += __shfl_xor_sync(0xffffffffu, l1, 2);
    float inv0 = 1.f / l0, inv1 = 1.f / l1;

    int b = bh / NHh, h = bh - (bh / NHh) * NHh;

    // ---- Epilogue: stage frag-layout tile in Ks, then coalesced write ----
    __syncthreads();
    {
        int t0v = (2 * tq) & 3, u0v = tq >> 1;
        int ibase = g * 16 + t0v * 4 + 2 * u0v;
        uint32_t* stg = Ks;
#pragma unroll
        for (int j = 0; j < 8; j++) {
            uint32_t* row = stg + (warp * 8 + j) * 128 + ibase;
            row[0] = f2tf32(oacc[j][0] * inv0);
            row[4] = f2tf32(oacc[j][1] * inv0);
            row[1] = f2tf32(oacc[j][2] * inv1);
            row[5] = f2tf32(oacc[j][3] * inv1);
        }
    }
    __syncthreads();
    {
        int m0b = (b * Tt + q0) >> 4;
        const int total = 7 * 8 * 32;      // float4 units (7 m-blocks)
        for (int i = tid; i < total; i += FTHREADS) {
            int rowc = i >> 5;
            int in4  = i & 31;
            int mbl = rowc >> 3, kbl = rowc & 7;
            uint4 v = *(const uint4*)&Ks[rowc * 128 + in4 * 4];
            *(uint4*)&g_o[(size_t)(m0b + mbl) * 6144 +
                          (h * 8 + kbl) * 128 + in4 * 4] = v;
        }
    }
}

// ---------------------------------------------------------------------------
// kernel_launch
// ---------------------------------------------------------------------------
extern "C" void kernel_launch(void* const* d_in, const int* in_sizes, int n_in,
                              void* d_out, int out_size)
{
    int base = 1;
    if (n_in >= 3 && in_sizes[1] == 1 && in_sizes[2] == 1) base = 3;

    const float* x = (const float*)d_in[0];
    const float* cw[3];
    const float* ga[3];
    const float* be[3];
    const float* me[3];
    const float* va[3];
    for (int i = 0; i < 3; i++) {
        cw[i] = (const float*)d_in[base + 5 * i + 0];
        ga[i] = (const float*)d_in[base + 5 * i + 1];
        be[i] = (const float*)d_in[base + 5 * i + 2];
        me[i] = (const float*)d_in[base + 5 * i + 3];
        va[i] = (const float*)d_in[base + 5 * i + 4];
    }
    const float* w_q    = (const float*)d_in[base + 15];
    const float* w_k    = (const float*)d_in[base + 16];
    const float* w_v    = (const float*)d_in[base + 17];
    const float* w_proj = (const float*)d_in[base + 18];
    const float* b_proj = (const float*)d_in[base + 19];
    float* out = (float*)d_out;

    static int attr_done = 0;
    if (!attr_done) {
        cudaFuncSetAttribute(qkv_mma_kernel,
                             cudaFuncAttributeMaxDynamicSharedMemorySize,
                             GEMM_DSMEM);
        cudaFuncSetAttribute(proj_mma_kernel,
                             cudaFuncAttributeMaxDynamicSharedMemorySize,
                             GEMM_DSMEM);
        cudaFuncSetAttribute(flash_kernel,
                             cudaFuncAttributeMaxDynamicSharedMemorySize,
                             FLASH_DSMEM);
        attr_done = 1;
    }

    wconv_kernel<<<(Cc * Cc + 255) / 256, 256>>>(w_q, w_k, w_v, w_proj);

    convbn_kernel<<<(Mm * Cc + 255) / 256, 256>>>(
        x,
        cw[0], ga[0], be[0], me[0], va[0],
        cw[1], ga[1], be[1], me[1], va[1],
        cw[2], ga[2], be[2], me[2], va[2]);

    qkv_mma_kernel<<<dim3(Mm / 128, Cc / 128, 3), 256, GEMM_DSMEM>>>();

    flash_kernel<<<dim3(7, BH), FTHREADS, FLASH_DSMEM>>>();

    proj_mma_kernel<<<dim3(Mm / 128, Cc / 128), 256, GEMM_DSMEM>>>(b_proj, out);
}